// round 8
// baseline (speedup 1.0000x reference)
#include <cuda_runtime.h>
#include <math.h>

// Reference reduces exactly to: out = 1.0 + gelu(bn(conv3x3_groups2(x4, local_w)))
// (softmax over the size-1 axis is identically 1; attn @ ones = row-sum of softmax = 1.)
//
// f32x2-packed conv: each thread computes 2 cols x 3 rows x 1 oc with packed
// fma.rn.f32x2. Input rows staged in smem in TWO parities:
//   A: [x0..x23]           -> pairs (x_even, x_even+1) aligned
//   B: [0, x0..x23, 0, pp] -> pairs (x_odd , x_odd+1 ) aligned, edges zero
// so every conv tap is one aligned LDS.64. Weights staged duplicated (k,k).

#define NPW 24
#define NPOS 576
#define ICG 64
#define ROWF 52              // floats per (ic,row): A[24] + B[28]
#define SROWS 5              // 3 output rows + 2 halo
#define THREADS 96           // 8 oc x 12 col-pairs
#define X_FLOATS (ICG*SROWS*ROWF)     // 16640 floats
#define W_ULL    (ICG*9*8)            // 4608 float2 (k,k) pairs
#define SMEM_BYTES (X_FLOATS*4 + W_ULL*8)   // 66560 + 36864 = 103424

typedef unsigned long long ull;

__device__ __forceinline__ void ffma2(ull& d, ull a, ull b) {
    asm("fma.rn.f32x2 %0, %1, %2, %0;" : "+l"(d) : "l"(a), "l"(b));
}

__global__ __launch_bounds__(THREADS)
void fused_c_kernel(const float* __restrict__ x,    // (2,128,24,24) flat
                    const float* __restrict__ lw,   // (128,64,3,3)
                    const float* __restrict__ gma,
                    const float* __restrict__ bta,
                    float* __restrict__ out)        // (2,128,24,24) flat
{
    extern __shared__ float sm[];
    float* sX = sm;                 // [ic][r][ A:24 | B:28 ]
    float* sWf = sm + X_FLOATS;     // 4608 float2, idx (ic*9+k)*8 + o

    int bid = blockIdx.x;
    const int ht  = bid & 7;
    const int occ = (bid >> 3) & 7;
    const int g   = (bid >> 6) & 1;
    const int b   = bid >> 7;

    const int h0 = ht * 3;
    const int ocBase = g * 64 + occ * 8;
    const int tid = threadIdx.x;

    // ---- stage X in dual-parity layout ----
    const float* xb = x + b * (128 * NPOS) + (g * ICG) * NPOS;
    #pragma unroll 5
    for (int i4 = tid; i4 < ICG * SROWS * 6; i4 += THREADS) {   // 1920 float4
        int ic  = i4 / 30;
        int rem = i4 - ic * 30;
        int r   = rem / 6;
        int w4  = rem - r * 6;
        int h   = h0 - 1 + r;
        float4 v = make_float4(0.f, 0.f, 0.f, 0.f);
        if ((unsigned)h < 24u)
            v = *reinterpret_cast<const float4*>(xb + ic * NPOS + h * NPW + w4 * 4);
        float* row = sX + (ic * SROWS + r) * ROWF;
        // copy A (aligned even pairs)
        *reinterpret_cast<float4*>(row + w4 * 4) = v;
        // copy B, shifted +1 (aligned odd pairs), zero edges
        float* Bp = row + 24;
        Bp[w4 * 4 + 1] = v.x;
        Bp[w4 * 4 + 2] = v.y;
        Bp[w4 * 4 + 3] = v.z;
        Bp[w4 * 4 + 4] = v.w;
        if (w4 == 0) Bp[0]  = 0.f;
        if (w4 == 5) Bp[25] = 0.f;
    }

    // ---- stage weights duplicated (k,k), layout (ic*9+k)*8 + o ----
    #pragma unroll 8
    for (int i = tid; i < W_ULL; i += THREADS) {
        int o   = i & 7;
        int rem = i >> 3;                 // ic*9 + k
        float v = lw[(ocBase + o) * 576 + rem];
        *reinterpret_cast<float2*>(sWf + 2 * i) = make_float2(v, v);
    }
    __syncthreads();

    // ---- compute: thread = (oc, col-pair), 3 rows x 2 cols via f32x2 ----
    const int wp = tid % 12;
    const int o  = tid / 12;      // 0..7
    const int w0 = wp * 2;

    ull acc[3];
    acc[0] = 0ull; acc[1] = 0ull; acc[2] = 0ull;

    const ull* sW2 = reinterpret_cast<const ull*>(sWf);

    #pragma unroll 4
    for (int ic = 0; ic < ICG; ic++) {
        const ull* wr = sW2 + ic * 72 + o;
        ull wv[9];
        #pragma unroll
        for (int k = 0; k < 9; k++) wv[k] = wr[k * 8];

        const float* xr = sX + ic * (SROWS * ROWF) + w0;
        ull a[SROWS], b0[SROWS], b2[SROWS];
        #pragma unroll
        for (int rr = 0; rr < SROWS; rr++) {
            const float* p = xr + rr * ROWF;
            a[rr]  = *reinterpret_cast<const ull*>(p);        // (x[w0],   x[w0+1])
            b0[rr] = *reinterpret_cast<const ull*>(p + 24);   // (x[w0-1], x[w0]  )
            b2[rr] = *reinterpret_cast<const ull*>(p + 26);   // (x[w0+1], x[w0+2])
        }

        #pragma unroll
        for (int r = 0; r < 3; r++) {
            #pragma unroll
            for (int kh = 0; kh < 3; kh++) {
                const int rr = r + kh;
                ffma2(acc[r], wv[kh * 3 + 0], b0[rr]);
                ffma2(acc[r], wv[kh * 3 + 1], a[rr]);
                ffma2(acc[r], wv[kh * 3 + 2], b2[rr]);
            }
        }
    }

    // ---- epilogue: BN affine + exact GELU + 1.0 ----
    const int oc = ocBase + o;
    const float ge = gma[oc] * 0.9999950000374997f;   // gamma / sqrt(1 + 1e-5)
    const float be = bta[oc];
    float* ob = out + b * (128 * NPOS) + oc * NPOS + h0 * NPW + w0;
    #pragma unroll
    for (int r = 0; r < 3; r++) {
        float2 v = *reinterpret_cast<float2*>(&acc[r]);
        float y0 = v.x * ge + be;
        float y1 = v.y * ge + be;
        float g0 = 0.5f * y0 * (1.0f + erff(y0 * 0.70710678118654752f));
        float g1 = 0.5f * y1 * (1.0f + erff(y1 * 0.70710678118654752f));
        *reinterpret_cast<float2*>(ob + r * NPW) = make_float2(1.0f + g0, 1.0f + g1);
    }
}

extern "C" void kernel_launch(void* const* d_in, const int* in_sizes, int n_in,
                              void* d_out, int out_size)
{
    const float* x   = (const float*)d_in[0];
    const float* lw  = (const float*)d_in[9];   // local_w
    const float* gma = (const float*)d_in[10];  // bnc1_gamma
    const float* bta = (const float*)d_in[11];  // bnc1_beta
    float* out = (float*)d_out;

    cudaFuncSetAttribute(fused_c_kernel,
                         cudaFuncAttributeMaxDynamicSharedMemorySize, SMEM_BYTES);
    fused_c_kernel<<<256, THREADS, SMEM_BYTES>>>(x, lw, gma, bta, out);
}

// round 11
// speedup vs baseline: 1.6758x; 1.6758x over previous
#include <cuda_runtime.h>
#include <math.h>

// Reference reduces exactly to: out = 1.0 + gelu(bn(conv3x3_groups2(x4, local_w)))
// (softmax over size-1 axis == 1; attn @ ones = 1.)
//
// Scalar conv (f32x2 measured as no fma-pipe win + chain serialization -> reverted).
// Occupancy fix: 4-way ic-split inside the block. 768 threads = 4 groups x
// (8 oc x 24 w); each group reduces 16 input channels into smem partials,
// then 192 threads combine 4 partials + BN + GELU. 4x warps vs R1 hides
// LDS/issue latency.

#define NPW 24
#define NPOS 576
#define ICG 64
#define ICS 16               // ic per split group
#define NSPLIT 4
#define OCB 8
#define RB 6                 // output rows per block
#define SROWS 8              // RB + 2 halo
#define THREADS 768          // NSPLIT * OCB * NPW
#define X_FLOATS (ICG*SROWS*NPW)          // 12288
#define W_FLOATS (ICG*9*OCB)              // 4608, [ic][k][oc]
#define P_FLOATS (OCB*NPW*RB*NSPLIT)      // 4608: [(o*24+w)*24 + r*4 + s]
#define SMEM_BYTES ((X_FLOATS + W_FLOATS + P_FLOATS)*4)   // 86016

__global__ __launch_bounds__(THREADS)
void fused_c_kernel(const float* __restrict__ x,    // (2,128,24,24) flat
                    const float* __restrict__ lw,   // (128,64,3,3)
                    const float* __restrict__ gma,
                    const float* __restrict__ bta,
                    float* __restrict__ out)        // (2,128,24,24) flat
{
    extern __shared__ float sm[];
    float* sX = sm;                       // [ic][r(8)][w(24)]
    float* sW = sm + X_FLOATS;            // [ic][k(9)][o(8)]
    float* sP = sm + X_FLOATS + W_FLOATS; // [(o,w)][r*4+s]

    int bid = blockIdx.x;
    const int ht  = bid & 3;  bid >>= 2;   // 4 row tiles of 6
    const int occ = bid & 7;  bid >>= 3;   // 8 oc chunks of 8
    const int g   = bid & 1;
    const int b   = bid >> 1;

    const int h0 = ht * RB;
    const int ocBase = g * 64 + occ * OCB;
    const int tid = threadIdx.x;

    // ---- stage input tile rows h0-1..h0+6 (float4), 3072 loads / 768 thr ----
    const float* xb = x + b * (128 * NPOS) + (g * ICG) * NPOS;
    #pragma unroll 4
    for (int i4 = tid; i4 < ICG * SROWS * 6; i4 += THREADS) {
        int ic  = i4 / 48;
        int rem = i4 - ic * 48;
        int r   = rem / 6;
        int w4  = rem - r * 6;
        int h   = h0 - 1 + r;
        float4 v = make_float4(0.f, 0.f, 0.f, 0.f);
        if ((unsigned)h < 24u)
            v = *reinterpret_cast<const float4*>(xb + ic * NPOS + h * NPW + w4 * 4);
        reinterpret_cast<float4*>(sX)[i4] = v;
    }

    // ---- stage weights transposed to [ic][k][oc] ----
    const float* wb = lw + ocBase * (ICG * 9);
    #pragma unroll 6
    for (int i = tid; i < OCB * ICG * 9; i += THREADS) {
        int o   = i / (ICG * 9);
        int rem = i - o * (ICG * 9);
        int ic  = rem / 9;
        int k   = rem - ic * 9;
        sW[(ic * 9 + k) * OCB + o] = wb[i];
    }
    __syncthreads();

    // ---- compute: thread = (split s, oc o, col w); reduce 16 ic ----
    const int s   = tid / 192;
    const int rem = tid - s * 192;
    const int o   = rem / NPW;
    const int w   = rem - o * NPW;
    const int icBase = s * ICS;

    float acc[RB];
    #pragma unroll
    for (int r = 0; r < RB; r++) acc[r] = 0.f;

    #pragma unroll 2
    for (int ii = 0; ii < ICS; ii++) {
        const int ic = icBase + ii;
        const float* wr = sW + ic * 9 * OCB + o;
        float wk[9];
        #pragma unroll
        for (int k = 0; k < 9; k++) wk[k] = wr[k * OCB];

        const float* xr = sX + ic * (SROWS * NPW);
        float xm[SROWS], xc[SROWS], xp[SROWS];
        #pragma unroll
        for (int r = 0; r < SROWS; r++) {
            const float* row = xr + r * NPW;
            xc[r] = row[w];
            xm[r] = (w > 0)  ? row[w - 1] : 0.f;
            xp[r] = (w < 23) ? row[w + 1] : 0.f;
        }

        #pragma unroll
        for (int r = 0; r < RB; r++) {
            #pragma unroll
            for (int kh = 0; kh < 3; kh++) {
                const int rr = r + kh;
                acc[r] += wk[kh * 3 + 0] * xm[rr];
                acc[r] += wk[kh * 3 + 1] * xc[rr];
                acc[r] += wk[kh * 3 + 2] * xp[rr];
            }
        }
    }

    // ---- write partials: sP[(o*24+w)*24 + r*4 + s] ----
    float* pp = sP + (o * NPW + w) * (RB * NSPLIT) + s;
    #pragma unroll
    for (int r = 0; r < RB; r++) pp[r * NSPLIT] = acc[r];
    __syncthreads();

    // ---- combine + BN + exact GELU + 1.0 (threads 0..191) ----
    if (tid < 192) {
        const int oc = ocBase + o;
        const float ge = gma[oc] * 0.9999950000374997f;  // gamma / sqrt(1+1e-5)
        const float be = bta[oc];
        const float4* pr = reinterpret_cast<const float4*>(
            sP + (o * NPW + w) * (RB * NSPLIT));
        float* ob = out + b * (128 * NPOS) + oc * NPOS + h0 * NPW + w;
        #pragma unroll
        for (int r = 0; r < RB; r++) {
            float4 p = pr[r];
            float y = (p.x + p.y + p.z + p.w) * ge + be;
            float gel = 0.5f * y * (1.0f + erff(y * 0.70710678118654752f));
            ob[r * NPW] = 1.0f + gel;
        }
    }
}

extern "C" void kernel_launch(void* const* d_in, const int* in_sizes, int n_in,
                              void* d_out, int out_size)
{
    const float* x   = (const float*)d_in[0];
    const float* lw  = (const float*)d_in[9];   // local_w
    const float* gma = (const float*)d_in[10];  // bnc1_gamma
    const float* bta = (const float*)d_in[11];  // bnc1_beta
    float* out = (float*)d_out;

    cudaFuncSetAttribute(fused_c_kernel,
                         cudaFuncAttributeMaxDynamicSharedMemorySize, SMEM_BYTES);
    fused_c_kernel<<<128, THREADS, SMEM_BYTES>>>(x, lw, gma, bta, out);
}

// round 16
// speedup vs baseline: 1.9775x; 1.1800x over previous
#include <cuda_runtime.h>
#include <math.h>

// out = 1.0 + gelu(bn(conv3x3_groups2(x4, local_w)))  (attention branch == 1 exactly)
//
// R11 structure (4-way ic-split, 768 thr: WIN) + instruction-diet:
//  - x rows padded (stride 32, data at [4+w], zeros at [3],[28]) -> no boundary
//    predication, 3 unconditional LDS per (ic,row)
//  - weights [o][ic][k0..8] (row stride 776) -> 2x LDS.128 + 1 LDS per ic
//  - partials stride 25 -> conflict-free split-combine

#define NPW 24
#define NPOS 576
#define ICG 64
#define ICS 16
#define NSPLIT 4
#define OCB 8
#define RB 6
#define SROWS 8
#define THREADS 768
#define XSTRIDE 32
#define WSTRIDE 776                       // 64*12 + 8 (debank o)
#define X_FLOATS (ICG*SROWS*XSTRIDE)      // 16384
#define W_FLOATS (OCB*WSTRIDE)            // 6208
#define P_FLOATS (OCB*NPW*25)             // 4800
#define SMEM_BYTES ((X_FLOATS + W_FLOATS + P_FLOATS)*4)   // 109568

__global__ __launch_bounds__(THREADS)
void fused_c_kernel(const float* __restrict__ x,    // (2,128,24,24) flat
                    const float* __restrict__ lw,   // (128,64,3,3)
                    const float* __restrict__ gma,
                    const float* __restrict__ bta,
                    float* __restrict__ out)        // (2,128,24,24) flat
{
    extern __shared__ float sm[];
    float* sX = sm;                       // [ic][r(8)][32]: data at 4+w
    float* sW = sm + X_FLOATS;            // [o][ic*12 + k]
    float* sP = sm + X_FLOATS + W_FLOATS; // [(o*24+w)*25 + r*4 + s]

    int bid = blockIdx.x;
    const int ht  = bid & 3;  bid >>= 2;
    const int occ = bid & 7;  bid >>= 3;
    const int g   = bid & 1;
    const int b   = bid >> 1;

    const int h0 = ht * RB;
    const int ocBase = g * 64 + occ * OCB;
    const int tid = threadIdx.x;

    // ---- zero the pad columns (indices 3 and 28 of every (ic,r) row) ----
    for (int i = tid; i < ICG * SROWS * 2; i += THREADS) {   // 1024
        int icr  = i >> 1;
        int side = i & 1;
        sX[icr * XSTRIDE + (side ? 28 : 3)] = 0.f;
    }

    // ---- stage input rows h0-1..h0+6, float4 at 4+w4*4 (16B aligned) ----
    const float* xb = x + b * (128 * NPOS) + (g * ICG) * NPOS;
    #pragma unroll 4
    for (int i4 = tid; i4 < ICG * SROWS * 6; i4 += THREADS) {   // 3072
        int ic  = i4 / 48;
        int rem = i4 - ic * 48;
        int r   = rem / 6;
        int w4  = rem - r * 6;
        int h   = h0 - 1 + r;
        float4 v = make_float4(0.f, 0.f, 0.f, 0.f);
        if ((unsigned)h < 24u)
            v = *reinterpret_cast<const float4*>(xb + ic * NPOS + h * NPW + w4 * 4);
        *reinterpret_cast<float4*>(sX + (ic * SROWS + r) * XSTRIDE + 4 + w4 * 4) = v;
    }

    // ---- stage weights: sW[o*776 + ic*12 + k] ----
    const float* wb = lw + ocBase * (ICG * 9);
    #pragma unroll 6
    for (int i = tid; i < OCB * ICG * 9; i += THREADS) {   // 4608
        int o   = i / 576;
        int rem = i - o * 576;      // ic*9 + k
        int ic  = rem / 9;
        int k   = rem - ic * 9;
        sW[o * WSTRIDE + ic * 12 + k] = wb[i];
    }
    __syncthreads();

    // ---- compute: thread = (split s, oc o, col w); reduce 16 ic ----
    const int s   = tid / 192;
    const int rem = tid - s * 192;
    const int o   = rem / NPW;
    const int w   = rem - o * NPW;

    float acc[RB];
    #pragma unroll
    for (int r = 0; r < RB; r++) acc[r] = 0.f;

    const float* wBase = sW + o * WSTRIDE + (s * ICS) * 12;
    const float* xBase = sX + (s * ICS) * (SROWS * XSTRIDE) + w;

    #pragma unroll 2
    for (int ii = 0; ii < ICS; ii++) {
        const float* wr = wBase + ii * 12;
        float4 wa = *reinterpret_cast<const float4*>(wr);       // k0..k3
        float4 wc = *reinterpret_cast<const float4*>(wr + 4);   // k4..k7
        float  w8 = wr[8];

        const float* xr = xBase + ii * (SROWS * XSTRIDE);
        float xm[SROWS], xc[SROWS], xp[SROWS];
        #pragma unroll
        for (int r = 0; r < SROWS; r++) {
            xm[r] = xr[r * XSTRIDE + 3];
            xc[r] = xr[r * XSTRIDE + 4];
            xp[r] = xr[r * XSTRIDE + 5];
        }

        #pragma unroll
        for (int r = 0; r < RB; r++) {
            acc[r] += wa.x * xm[r]     + wa.y * xc[r]     + wa.z * xp[r];
            acc[r] += wa.w * xm[r + 1] + wc.x * xc[r + 1] + wc.y * xp[r + 1];
            acc[r] += wc.z * xm[r + 2] + wc.w * xc[r + 2] + w8  * xp[r + 2];
        }
    }

    // ---- write partials (stride 25: conflict-free) ----
    float* pp = sP + (o * NPW + w) * 25 + s;
    #pragma unroll
    for (int r = 0; r < RB; r++) pp[r * NSPLIT] = acc[r];
    __syncthreads();

    // ---- combine + BN + exact GELU + 1.0 (threads 0..191) ----
    if (tid < 192) {
        const int oc = ocBase + o;
        const float ge = gma[oc] * 0.9999950000374997f;  // gamma / sqrt(1+1e-5)
        const float be = bta[oc];
        const float* pr = sP + (o * NPW + w) * 25;
        float* ob = out + b * (128 * NPOS) + oc * NPOS + h0 * NPW + w;
        #pragma unroll
        for (int r = 0; r < RB; r++) {
            float y = ((pr[r * 4 + 0] + pr[r * 4 + 1]) +
                       (pr[r * 4 + 2] + pr[r * 4 + 3])) * ge + be;
            float gel = 0.5f * y * (1.0f + erff(y * 0.70710678118654752f));
            ob[r * NPW] = 1.0f + gel;
        }
    }
}

extern "C" void kernel_launch(void* const* d_in, const int* in_sizes, int n_in,
                              void* d_out, int out_size)
{
    const float* x   = (const float*)d_in[0];
    const float* lw  = (const float*)d_in[9];   // local_w
    const float* gma = (const float*)d_in[10];  // bnc1_gamma
    const float* bta = (const float*)d_in[11];  // bnc1_beta
    float* out = (float*)d_out;

    cudaFuncSetAttribute(fused_c_kernel,
                         cudaFuncAttributeMaxDynamicSharedMemorySize, SMEM_BYTES);
    fused_c_kernel<<<128, THREADS, SMEM_BYTES>>>(x, lw, gma, bta, out);
}